// round 16
// baseline (speedup 1.0000x reference)
#include <cuda_runtime.h>
#include <cuda_fp16.h>
#include <cstdint>
#include <math.h>

#define Bn   4
#define Tn   1024
#define Cn   2048
#define Hn   16
#define HDn  128
#define NBLK 1024
#define M_ALL (Bn*Tn)          // 4096
#define N_QKV (3*Cn)           // 6144

// ---------------- scratch (device globals; no runtime allocation) -------------
__device__ float g_t[Bn*Tn];
__device__ float g_cs[M_ALL*64], g_sn[M_ALL*64];     // RoPE tables [row][j]
__device__ __half g_xh[(size_t)M_ALL*Cn];
__device__ __half g_Wa[(size_t)Cn*N_QKV];
__device__ __half g_Wp[(size_t)Cn*Cn];
__device__ __half g_yh[(size_t)M_ALL*Cn];
#define QKV_ELEMS ((size_t)Bn*Hn*Tn*HDn)
__device__ __half g_qh[QKV_ELEMS];                   // Q single
__device__ __half g_kh[QKV_ELEMS];                   // K single
__device__ __half g_vh[QKV_ELEMS];                   // V single

__device__ __forceinline__ uint32_t smem_u32(const void* p) {
    uint32_t a;
    asm("{ .reg .u64 t; cvta.to.shared.u64 t, %1; cvt.u32.u64 %0, t; }"
        : "=r"(a) : "l"(p));
    return a;
}
#define CP_ASYNC16(sa, gp) \
    asm volatile("cp.async.cg.shared.global [%0], [%1], 16;" :: "r"(sa), "l"(gp))
#define CP_COMMIT() asm volatile("cp.async.commit_group;" ::: "memory")
#define CP_WAIT(n)  asm volatile("cp.async.wait_group %0;" :: "n"(n) : "memory")

#define LDSM4(f, ad) \
    asm volatile("ldmatrix.sync.aligned.m8n8.x4.shared.b16 {%0,%1,%2,%3}, [%4];" \
        : "=r"((f)[0]), "=r"((f)[1]), "=r"((f)[2]), "=r"((f)[3]) : "r"(ad))
#define LDSM4T(f, ad) \
    asm volatile("ldmatrix.sync.aligned.m8n8.x4.trans.shared.b16 {%0,%1,%2,%3}, [%4];" \
        : "=r"((f)[0]), "=r"((f)[1]), "=r"((f)[2]), "=r"((f)[3]) : "r"(ad))
#define MMA16(cp, a, b0, b1) \
    asm volatile("mma.sync.aligned.m16n8k16.row.col.f32.f16.f16.f32 " \
        "{%0,%1,%2,%3}, {%4,%5,%6,%7}, {%8,%9}, {%0,%1,%2,%3};" \
        : "+f"((cp)[0]), "+f"((cp)[1]), "+f"((cp)[2]), "+f"((cp)[3]) \
        : "r"((a)[0]), "r"((a)[1]), "r"((a)[2]), "r"((a)[3]), "r"(b0), "r"(b1))

__device__ __forceinline__ uint32_t pack16(float x, float y) {
    __half2 h = __floats2half2_rn(x, y);
    return *(uint32_t*)&h;
}

// ---------------- prep kernels ------------------------------------------------
__global__ void t_kernel(const int* __restrict__ tok) {
    __shared__ int   cnt[NBLK];
    __shared__ float buf[Bn][Tn];
    int tid = threadIdx.x;                 // 1024 threads
    cnt[tid] = 0;
    __syncthreads();
    for (int i = tid; i < Bn*Tn; i += blockDim.x)
        atomicAdd(&cnt[tok[i]], 1);
    __syncthreads();
    #pragma unroll
    for (int b = 0; b < Bn; b++)
        buf[b][tid] = 1.0f / ((float)cnt[tok[b*Tn + tid]] + 1e-10f);
    __syncthreads();
    #pragma unroll
    for (int off = 1; off < Tn; off <<= 1) {
        float v[Bn];
        #pragma unroll
        for (int b = 0; b < Bn; b++)
            v[b] = (tid >= off) ? buf[b][tid - off] : 0.0f;
        __syncthreads();
        #pragma unroll
        for (int b = 0; b < Bn; b++) buf[b][tid] += v[b];
        __syncthreads();
    }
    #pragma unroll
    for (int b = 0; b < Bn; b++)
        g_t[b*Tn + tid] = buf[b][tid];
}

__global__ void rope_kernel() {
    int idx = blockIdx.x * blockDim.x + threadIdx.x;  // M_ALL*64
    int row = idx >> 6, j = idx & 63;
    float invf = (float)exp(-(double)j * (9.210340371976184 / 64.0));
    float ang = g_t[row] * invf;
    float sn, cs;
    sincosf(ang, &sn, &cs);
    g_cs[idx] = cs;
    g_sn[idx] = sn;
}

// fused 3-segment f32 -> fp16 conversion (x, Wa, Wp in one launch)
#define N4_X  (M_ALL*Cn/4)
#define N4_WA (Cn*N_QKV/4)
#define N4_WP (Cn*Cn/4)
#define N4_ALL (N4_X + N4_WA + N4_WP)
__global__ void cvt16_fused(const float* __restrict__ x,
                            const float* __restrict__ Wa,
                            const float* __restrict__ Wp) {
    int i = blockIdx.x * blockDim.x + threadIdx.x;
    const float* src;
    __half* dst;
    int li;
    if (i < N4_X)                 { src = x;  dst = g_xh; li = i; }
    else if (i < N4_X + N4_WA)    { src = Wa; dst = g_Wa; li = i - N4_X; }
    else                          { src = Wp; dst = g_Wp; li = i - N4_X - N4_WA; }
    float4 v = ((const float4*)src)[li];
    __half h[4] = {__float2half_rn(v.x), __float2half_rn(v.y),
                   __float2half_rn(v.z), __float2half_rn(v.w)};
    ((uint2*)dst)[li] = *(uint2*)h;
}

// ==================== shared GEMM building blocks (R13) =======================
#define GT   256
#define NPERS 296               // persistent grid: 148 SMs x 2 CTAs
#define ST2_BYTES 32768         // stage: A 16K (128 rows x 128B) | B 16K (64 k x 256B)
#define OFF_B2   16384
#define GEMM1_SMEM (3*ST2_BYTES)
#define STG_STRIDE 129
#define GEMM_QKV_SMEM (3*ST2_BYTES)

__device__ __forceinline__ void ldm_a2(uint32_t base, int rowbase, int s,
                                       uint32_t* f, int lane) {
    int row = rowbase + (lane & 7) + 8*((lane>>3)&1);
    int ch  = 2*s + (lane>>4);
    uint32_t a = base + row*128 + (((uint32_t)(ch ^ (row & 7))) << 4);
    LDSM4(f, a);
}
__device__ __forceinline__ void ldm_b2(uint32_t base, int s, int cb,
                                       uint32_t* f, int lane) {
    int k  = 16*s + (lane & 7) + 8*((lane>>3)&1);
    int ch = cb + (lane>>4);
    uint32_t a = base + k*256 + (((uint32_t)(ch ^ (k&7))) << 4);
    LDSM4T(f, a);
}

__device__ __forceinline__ void issue_stage2(
        const __half* __restrict__ Ah, const __half* __restrict__ Bh,
        int K, int N, int m0, int n0, int k0, uint32_t st, int tid) {
    #pragma unroll
    for (int i = 0; i < 4; i++) {
        int g = tid + i*GT;
        int m = g >> 3, c = g & 7;
        size_t ga = (size_t)(m0 + m)*K + k0 + c*8;
        uint32_t sa = st + m*128 + (((uint32_t)(c ^ (m & 7))) << 4);
        CP_ASYNC16(sa, Ah + ga);
    }
    #pragma unroll
    for (int i = 0; i < 4; i++) {
        int g = tid + i*GT;
        int k = g >> 4, cn = g & 15;
        size_t gb = (size_t)(k0 + k)*N + n0 + cn*8;
        uint32_t sb = st + OFF_B2 + k*256 + (((uint32_t)(cn ^ (k&7))) << 4);
        CP_ASYNC16(sb, Bh + gb);
    }
}

__device__ __forceinline__ void gemm1_mainloop(
        const __half* __restrict__ Ah, const __half* __restrict__ Bh,
        int K, int N, int m0, int n0, uint32_t sb, int tid,
        int lane, int wm, int wn, float acc[4][4][4]) {
    const int NK = K / 64;
    #pragma unroll
    for (int p = 0; p < 2; p++) {
        issue_stage2(Ah, Bh, K, N, m0, n0, p*64, sb + p*ST2_BYTES, tid);
        CP_COMMIT();
    }
    for (int kt = 0; kt < NK; kt++) {
        CP_WAIT(1);
        __syncthreads();
        uint32_t st = sb + (kt % 3)*ST2_BYTES;
        if (kt + 2 < NK)
            issue_stage2(Ah, Bh, K, N, m0, n0, (kt+2)*64,
                         sb + ((kt+2) % 3)*ST2_BYTES, tid);
        CP_COMMIT();
        #pragma unroll
        for (int s = 0; s < 4; s++) {
            uint32_t af[4][4];
            #pragma unroll
            for (int mi = 0; mi < 4; mi++)
                ldm_a2(st, wm*64 + mi*16, s, af[mi], lane);
            #pragma unroll
            for (int nj = 0; nj < 2; nj++) {
                uint32_t bf[4];
                ldm_b2(st + OFF_B2, s, wn*4 + nj*2, bf, lane);
                #pragma unroll
                for (int mi = 0; mi < 4; mi++) {
                    MMA16(acc[mi][nj*2],   af[mi], bf[0], bf[1]);
                    MMA16(acc[mi][nj*2+1], af[mi], bf[2], bf[3]);
                }
            }
        }
    }
    CP_WAIT(0);
    __syncthreads();
}

// ==================== QKV GEMM: persistent, 1-term, fused RoPE epilogue =======
__global__ __launch_bounds__(GT, 2)
void hmma_gemm_qkv(const __half* __restrict__ Ah, const __half* __restrict__ Bh,
                   const float* __restrict__ cum) {
    extern __shared__ char smraw[];
    uint32_t sb = smem_u32(smraw);
    int tid = threadIdx.x;
    int lane = tid & 31, warp = tid >> 5;
    int wm = warp >> 2, wn = warp & 3;
    const int NTILES = (N_QKV/128) * (M_ALL/128);    // 48 * 32 = 1536

    for (int tile = blockIdx.x; tile < NTILES; tile += gridDim.x) {
        int m0 = (tile / 48) * 128;
        int n0 = (tile % 48) * 128;

        float acc[4][4][4];
        #pragma unroll
        for (int a = 0; a < 4; a++)
            #pragma unroll
            for (int b = 0; b < 4; b++)
                #pragma unroll
                for (int c = 0; c < 4; c++) acc[a][b][c] = 0.0f;

        gemm1_mainloop(Ah, Bh, Cn, N_QKV, m0, n0, sb, tid, lane, wm, wn, acc);

        float* stg = (float*)smraw;
        int rq = lane >> 2, cq = (lane & 3) << 1;
        #pragma unroll
        for (int mi = 0; mi < 4; mi++) {
            int r = wm*64 + mi*16 + rq;
            #pragma unroll
            for (int ni = 0; ni < 4; ni++) {
                int cc = wn*32 + ni*8 + cq;
                stg[r*STG_STRIDE + cc]       = acc[mi][ni][0];
                stg[r*STG_STRIDE + cc + 1]   = acc[mi][ni][1];
                stg[(r+8)*STG_STRIDE + cc]   = acc[mi][ni][2];
                stg[(r+8)*STG_STRIDE + cc+1] = acc[mi][ni][3];
            }
        }
        __syncthreads();

        int r   = tid & 127;
        int seg = tid >> 7;
        int row = m0 + r;
        int bb = row >> 10, tt = row & 1023;
        int sec  = n0 >> 11;                   // 0=q, 1=k, 2=v
        int habs = (n0 & 2047) >> 7;
        float csc = cum[bb*Tn + tt];
        size_t obase = (((size_t)(bb*Hn + habs))*Tn + tt) * HDn;
        const float* srow = stg + r*STG_STRIDE;
        const float* csr = g_cs + row*64;
        const float* snr = g_sn + row*64;

        if (sec == 2) {
            float ev = expf(csc);
            int c0 = seg*64;
            #pragma unroll
            for (int c = c0; c < c0 + 64; c += 2)
                ((uint32_t*)g_vh)[(obase + c) >> 1] = pack16(srow[c]*ev, srow[c+1]*ev);
        } else {
            float ovr = (sec == 0) ? 1.0f : csc;
            __half* dst = (sec == 0) ? g_qh : g_kh;
            int j0 = seg*32;
            #pragma unroll
            for (int j = j0; j < j0 + 32; j += 2) {
                float s1a = srow[j],   s2a = srow[j+64];
                float s1b = srow[j+1], s2b = srow[j+65];
                float ca = csr[j], sa = snr[j], cb = csr[j+1], sbn = snr[j+1];
                float lo_a = s1a*ca - s2a*sa, hi_a = s2a*ca + s1a*sa;
                float lo_b = s1b*cb - s2b*sbn, hi_b = s2b*cb + s1b*sbn;
                if (j == 62) hi_b = ovr;
                ((uint32_t*)dst)[(obase + j) >> 1]      = pack16(lo_a, lo_b);
                ((uint32_t*)dst)[(obase + 64 + j) >> 1] = pack16(hi_a, hi_b);
            }
        }
        __syncthreads();   // staging fully read before next tile's cp.async
    }
}

// ==================== proj GEMM: persistent, 1-term fp16 ======================
__global__ __launch_bounds__(GT, 2)
void hmma_gemm_o(const __half* __restrict__ Ah, const __half* __restrict__ Bh,
                 float* __restrict__ Cg, int M, int N, int K) {
    extern __shared__ char smraw[];
    uint32_t sb = smem_u32(smraw);
    int tid = threadIdx.x;
    int lane = tid & 31, warp = tid >> 5;
    int wm = warp >> 2, wn = warp & 3;
    int ncols = N / 128;
    int ntiles = (M / 128) * ncols;

    for (int tile = blockIdx.x; tile < ntiles; tile += gridDim.x) {
        int m0 = (tile / ncols) * 128;
        int n0 = (tile % ncols) * 128;

        float acc[4][4][4];
        #pragma unroll
        for (int a = 0; a < 4; a++)
            #pragma unroll
            for (int b = 0; b < 4; b++)
                #pragma unroll
                for (int c = 0; c < 4; c++) acc[a][b][c] = 0.0f;

        gemm1_mainloop(Ah, Bh, K, N, m0, n0, sb, tid, lane, wm, wn, acc);

        int rq = lane >> 2, cq = (lane & 3) << 1;
        #pragma unroll
        for (int mi = 0; mi < 4; mi++) {
            int r = m0 + wm*64 + mi*16 + rq;
            #pragma unroll
            for (int ni = 0; ni < 4; ni++) {
                int cc = n0 + wn*32 + ni*8 + cq;
                *(float2*)&Cg[(size_t)r*N + cc] =
                    make_float2(acc[mi][ni][0], acc[mi][ni][1]);
                *(float2*)&Cg[(size_t)(r+8)*N + cc] =
                    make_float2(acc[mi][ni][2], acc[mi][ni][3]);
            }
        }
    }
}

// ---------------- flash attention: 64 q-rows/CTA, heavy-first ----------------
// smem: Q 16K | 2 x (K 16K, V 16K) | 2 x pads 256B
#define A_Q    0
#define A_BUF  16384
#define A_PADS (16384 + 65536)
#define ATTN_SMEM (A_PADS + 512)
#define SCALE_A 0.08838834764831843f
#define NEG_A  -1.0e30f

__device__ __forceinline__ void attn_load_tile(uint32_t sb, int buf, int bh,
                                               int b, int kb,
                                               const int* __restrict__ pad,
                                               int tid) {
    uint32_t base = sb + A_BUF + buf*32768;
    #pragma unroll
    for (int i = 0; i < 8; i++) {
        int g = tid + i*128;
        int row = g >> 4, ch = g & 15;
        size_t off = ((size_t)bh*Tn + kb + row)*HDn + ch*8;
        uint32_t sw = row*256 + (((uint32_t)(ch ^ (row & 7))) << 4);
        CP_ASYNC16(base + sw,         g_kh + off);
        CP_ASYNC16(base + 16384 + sw, g_vh + off);
    }
    if (tid < 16)
        CP_ASYNC16(sb + A_PADS + buf*256 + tid*16, pad + b*Tn + kb + tid*4);
}

__global__ __launch_bounds__(128, 2)
void attn_hmma(const int* __restrict__ pad) {
    extern __shared__ char smraw[];
    uint32_t sb = smem_u32(smraw);
    int tid = threadIdx.x, lane = tid & 31, w = tid >> 5;
    int mtile = 15 - blockIdx.x;           // heavy tiles launch first
    int bh = blockIdx.y;
    int b = bh >> 4, h = bh & 15;
    int q0 = mtile*64;

    #pragma unroll
    for (int i = 0; i < 8; i++) {
        int g = tid + i*128;
        int row = g >> 4, ch = g & 15;
        size_t off = ((size_t)bh*Tn + q0 + row)*HDn + ch*8;
        uint32_t sw = row*256 + (((uint32_t)(ch ^ (row & 7))) << 4);
        CP_ASYNC16(sb + A_Q + sw, g_qh + off);
    }
    attn_load_tile(sb, 0, bh, b, 0, pad, tid);
    CP_COMMIT();

    float o[16][4];
    #pragma unroll
    for (int nt = 0; nt < 16; nt++)
        #pragma unroll
        for (int e = 0; e < 4; e++) o[nt][e] = 0.0f;
    float m0f = -3.0e38f, m1f = -3.0e38f, l0f = 0.0f, l1f = 0.0f;

    int rq = lane >> 2, cq2 = (lane & 3) << 1;
    int qg0 = q0 + w*16 + rq, qg1 = qg0 + 8;

    for (int n = 0; n <= mtile; n++) {
        int cur = n & 1;
        if (n < mtile) {
            attn_load_tile(sb, cur ^ 1, bh, b, (n+1)*64, pad, tid);
            CP_COMMIT();
            CP_WAIT(1);
        } else {
            CP_WAIT(0);
        }
        __syncthreads();

        uint32_t bufb = sb + A_BUF + cur*32768;
        int kb = n*64;

        float sa[8][4];
        #pragma unroll
        for (int nt = 0; nt < 8; nt++)
            #pragma unroll
            for (int e = 0; e < 4; e++) sa[nt][e] = 0.0f;

        #pragma unroll
        for (int s = 0; s < 8; s++) {
            uint32_t qhf[4];
            {
                int row = w*16 + (lane & 7) + 8*((lane>>3)&1);
                int ch  = 2*s + (lane>>4);
                uint32_t ad = sb + A_Q + row*256 +
                              (((uint32_t)(ch ^ (row & 7))) << 4);
                LDSM4(qhf, ad);
            }
            #pragma unroll
            for (int g4 = 0; g4 < 4; g4++) {
                uint32_t khf[4];
                int key = g4*16 + (lane & 7) + 8*((lane>>3)&1);
                int ch  = 2*s + (lane>>4);
                uint32_t ad = bufb + key*256 +
                              (((uint32_t)(ch ^ (key & 7))) << 4);
                LDSM4(khf, ad);
                MMA16(sa[2*g4],   qhf, khf[0], khf[2]);
                MMA16(sa[2*g4+1], qhf, khf[1], khf[3]);
            }
        }

        const int* padp = (const int*)(smraw + A_PADS + cur*256);
        #pragma unroll
        for (int nt = 0; nt < 8; nt++) {
            int kc = nt*8 + cq2;
            int kg = kb + kc;
            int p0 = padp[kc], p1 = padp[kc+1];
            float v;
            v = sa[nt][0]*SCALE_A; if (kg   > qg0 || !p0) v = NEG_A; sa[nt][0] = v;
            v = sa[nt][1]*SCALE_A; if (kg+1 > qg0 || !p1) v = NEG_A; sa[nt][1] = v;
            v = sa[nt][2]*SCALE_A; if (kg   > qg1 || !p0) v = NEG_A; sa[nt][2] = v;
            v = sa[nt][3]*SCALE_A; if (kg+1 > qg1 || !p1) v = NEG_A; sa[nt][3] = v;
        }

        float mx0 = -3.0e38f, mx1 = -3.0e38f;
        #pragma unroll
        for (int nt = 0; nt < 8; nt++) {
            mx0 = fmaxf(mx0, fmaxf(sa[nt][0], sa[nt][1]));
            mx1 = fmaxf(mx1, fmaxf(sa[nt][2], sa[nt][3]));
        }
        mx0 = fmaxf(mx0, __shfl_xor_sync(0xffffffffu, mx0, 1));
        mx0 = fmaxf(mx0, __shfl_xor_sync(0xffffffffu, mx0, 2));
        mx1 = fmaxf(mx1, __shfl_xor_sync(0xffffffffu, mx1, 1));
        mx1 = fmaxf(mx1, __shfl_xor_sync(0xffffffffu, mx1, 2));
        float mn0 = fmaxf(m0f, mx0), mn1 = fmaxf(m1f, mx1);
        float al0 = __expf(m0f - mn0), al1 = __expf(m1f - mn1);
        m0f = mn0; m1f = mn1;
        float s0 = 0.0f, s1 = 0.0f;
        #pragma unroll
        for (int nt = 0; nt < 8; nt++) {
            sa[nt][0] = __expf(sa[nt][0] - mn0); s0 += sa[nt][0];
            sa[nt][1] = __expf(sa[nt][1] - mn0); s0 += sa[nt][1];
            sa[nt][2] = __expf(sa[nt][2] - mn1); s1 += sa[nt][2];
            sa[nt][3] = __expf(sa[nt][3] - mn1); s1 += sa[nt][3];
        }
        s0 += __shfl_xor_sync(0xffffffffu, s0, 1);
        s0 += __shfl_xor_sync(0xffffffffu, s0, 2);
        s1 += __shfl_xor_sync(0xffffffffu, s1, 1);
        s1 += __shfl_xor_sync(0xffffffffu, s1, 2);
        l0f = l0f*al0 + s0;
        l1f = l1f*al1 + s1;
        #pragma unroll
        for (int nt = 0; nt < 16; nt++) {
            o[nt][0] *= al0; o[nt][1] *= al0;
            o[nt][2] *= al1; o[nt][3] *= al1;
        }

        #pragma unroll
        for (int j = 0; j < 4; j++) {
            uint32_t aph[4];
            aph[0] = pack16(sa[2*j][0],   sa[2*j][1]);
            aph[1] = pack16(sa[2*j][2],   sa[2*j][3]);
            aph[2] = pack16(sa[2*j+1][0], sa[2*j+1][1]);
            aph[3] = pack16(sa[2*j+1][2], sa[2*j+1][3]);
            #pragma unroll
            for (int u = 0; u < 8; u++) {
                uint32_t vhf[4];
                int key = j*16 + (lane & 7) + 8*((lane>>3)&1);
                int ch  = u*2 + (lane>>4);
                uint32_t ad = bufb + 16384 + key*256 +
                              (((uint32_t)(ch ^ (key & 7))) << 4);
                LDSM4T(vhf, ad);
                MMA16(o[2*u],   aph, vhf[0], vhf[1]);
                MMA16(o[2*u+1], aph, vhf[2], vhf[3]);
            }
        }
        __syncthreads();
    }

    float i0 = 1.0f / l0f, i1 = 1.0f / l1f;
    size_t r0g = (size_t)(b*Tn + q0 + w*16 + rq)*Cn + h*HDn;
    size_t r1g = r0g + (size_t)8*Cn;
    #pragma unroll
    for (int nt = 0; nt < 16; nt++) {
        int col = nt*8 + cq2;
        ((uint32_t*)g_yh)[(r0g + col) >> 1] = pack16(o[nt][0]*i0, o[nt][1]*i0);
        ((uint32_t*)g_yh)[(r1g + col) >> 1] = pack16(o[nt][2]*i1, o[nt][3]*i1);
    }
}

// ---------------- launcher ----------------------------------------------------
extern "C" void kernel_launch(void* const* d_in, const int* in_sizes, int n_in,
                              void* d_out, int out_size) {
    const float* x    = (const float*)d_in[0];
    const float* cum  = (const float*)d_in[1];
    const int*   tok  = (const int*)d_in[2];
    const int*   padm = (const int*)d_in[3];
    const float* Wa   = (const float*)d_in[4];
    const float* Wp   = (const float*)d_in[5];
    float* out = (float*)d_out;

    __half *xh, *wa, *wp, *yh;
    cudaGetSymbolAddress((void**)&xh, g_xh);
    cudaGetSymbolAddress((void**)&wa, g_Wa);
    cudaGetSymbolAddress((void**)&wp, g_Wp);
    cudaGetSymbolAddress((void**)&yh, g_yh);

    cudaFuncSetAttribute(attn_hmma,
                         cudaFuncAttributeMaxDynamicSharedMemorySize, ATTN_SMEM);
    cudaFuncSetAttribute(hmma_gemm_qkv,
                         cudaFuncAttributeMaxDynamicSharedMemorySize, GEMM_QKV_SMEM);
    cudaFuncSetAttribute(hmma_gemm_o,
                         cudaFuncAttributeMaxDynamicSharedMemorySize, GEMM1_SMEM);

    t_kernel<<<1, 1024>>>(tok);
    rope_kernel<<<(M_ALL*64)/256, 256>>>();
    cvt16_fused<<<N4_ALL/256, 256>>>(x, Wa, Wp);

    hmma_gemm_qkv<<<NPERS, GT, GEMM_QKV_SMEM>>>(xh, wa, cum);

    attn_hmma<<<dim3(Tn/64, Bn*Hn), 128, ATTN_SMEM>>>(padm);

    hmma_gemm_o<<<NPERS, GT, GEMM1_SMEM>>>(yh, wp, out, M_ALL, Cn, Cn);
}

// round 17
// speedup vs baseline: 1.0417x; 1.0417x over previous
#include <cuda_runtime.h>
#include <cuda_fp16.h>
#include <cstdint>
#include <math.h>

#define Bn   4
#define Tn   1024
#define Cn   2048
#define Hn   16
#define HDn  128
#define NBLK 1024
#define M_ALL (Bn*Tn)          // 4096
#define N_QKV (3*Cn)           // 6144

// ---------------- scratch (device globals; no runtime allocation) -------------
__device__ float g_t[Bn*Tn];
__device__ float g_cs[M_ALL*64], g_sn[M_ALL*64];     // RoPE tables [row][j]
__device__ __half g_xh[(size_t)M_ALL*Cn];
__device__ __half g_Wa[(size_t)Cn*N_QKV];
__device__ __half g_Wp[(size_t)Cn*Cn];
__device__ __half g_yh[(size_t)M_ALL*Cn];
#define QKV_ELEMS ((size_t)Bn*Hn*Tn*HDn)
__device__ __half g_qh[QKV_ELEMS];                   // Q single
__device__ __half g_kh[QKV_ELEMS];                   // K single
__device__ __half g_vh[QKV_ELEMS];                   // V single

__device__ __forceinline__ uint32_t smem_u32(const void* p) {
    uint32_t a;
    asm("{ .reg .u64 t; cvta.to.shared.u64 t, %1; cvt.u32.u64 %0, t; }"
        : "=r"(a) : "l"(p));
    return a;
}
#define CP_ASYNC16(sa, gp) \
    asm volatile("cp.async.cg.shared.global [%0], [%1], 16;" :: "r"(sa), "l"(gp))
#define CP_COMMIT() asm volatile("cp.async.commit_group;" ::: "memory")
#define CP_WAIT(n)  asm volatile("cp.async.wait_group %0;" :: "n"(n) : "memory")

#define LDSM4(f, ad) \
    asm volatile("ldmatrix.sync.aligned.m8n8.x4.shared.b16 {%0,%1,%2,%3}, [%4];" \
        : "=r"((f)[0]), "=r"((f)[1]), "=r"((f)[2]), "=r"((f)[3]) : "r"(ad))
#define LDSM4T(f, ad) \
    asm volatile("ldmatrix.sync.aligned.m8n8.x4.trans.shared.b16 {%0,%1,%2,%3}, [%4];" \
        : "=r"((f)[0]), "=r"((f)[1]), "=r"((f)[2]), "=r"((f)[3]) : "r"(ad))
#define MMA16(cp, a, b0, b1) \
    asm volatile("mma.sync.aligned.m16n8k16.row.col.f32.f16.f16.f32 " \
        "{%0,%1,%2,%3}, {%4,%5,%6,%7}, {%8,%9}, {%0,%1,%2,%3};" \
        : "+f"((cp)[0]), "+f"((cp)[1]), "+f"((cp)[2]), "+f"((cp)[3]) \
        : "r"((a)[0]), "r"((a)[1]), "r"((a)[2]), "r"((a)[3]), "r"(b0), "r"(b1))

__device__ __forceinline__ uint32_t pack16(float x, float y) {
    __half2 h = __floats2half2_rn(x, y);
    return *(uint32_t*)&h;
}

// ---------------- fused prep: block 0 = t-scan, blocks >=1 = f32->fp16 cvt ----
#define N4_X  (M_ALL*Cn/4)
#define N4_WA (Cn*N_QKV/4)
#define N4_WP (Cn*Cn/4)
#define N4_ALL (N4_X + N4_WA + N4_WP)      // 6291456
#define CVT_BLOCKS (N4_ALL/1024)           // 6144

__global__ void prep_fused(const int* __restrict__ tok,
                           const float* __restrict__ x,
                           const float* __restrict__ Wa,
                           const float* __restrict__ Wp) {
    __shared__ int   cnt[NBLK];
    __shared__ float buf[Tn];
    int tid = threadIdx.x;                 // 1024 threads
    if (blockIdx.x == 0) {
        // ---- global histogram + per-batch cumsum (R13-serial) ----
        cnt[tid] = 0;
        __syncthreads();
        for (int i = tid; i < Bn*Tn; i += blockDim.x)
            atomicAdd(&cnt[tok[i]], 1);
        __syncthreads();
        for (int b = 0; b < Bn; b++) {
            float r = 1.0f / ((float)cnt[tok[b*Tn + tid]] + 1e-10f);
            buf[tid] = r;
            __syncthreads();
            #pragma unroll
            for (int off = 1; off < Tn; off <<= 1) {
                float v = (tid >= off) ? buf[tid - off] : 0.0f;
                __syncthreads();
                buf[tid] += v;
                __syncthreads();
            }
            g_t[b*Tn + tid] = buf[tid];
            __syncthreads();
        }
    } else {
        // ---- f32 -> fp16 conversion, 1024 float4s per block ----
        int i = (blockIdx.x - 1) * 1024 + tid;
        const float* src;
        __half* dst;
        int li;
        if (i < N4_X)               { src = x;  dst = g_xh; li = i; }
        else if (i < N4_X + N4_WA)  { src = Wa; dst = g_Wa; li = i - N4_X; }
        else                        { src = Wp; dst = g_Wp; li = i - N4_X - N4_WA; }
        float4 v = ((const float4*)src)[li];
        __half h[4] = {__float2half_rn(v.x), __float2half_rn(v.y),
                       __float2half_rn(v.z), __float2half_rn(v.w)};
        ((uint2*)dst)[li] = *(uint2*)h;
    }
}

__global__ void rope_kernel() {
    int idx = blockIdx.x * blockDim.x + threadIdx.x;  // M_ALL*64
    int row = idx >> 6, j = idx & 63;
    float invf = (float)exp(-(double)j * (9.210340371976184 / 64.0));
    float ang = g_t[row] * invf;
    float sn, cs;
    sincosf(ang, &sn, &cs);
    g_cs[idx] = cs;
    g_sn[idx] = sn;
}

// ==================== shared GEMM building blocks (R13) =======================
#define GT   256
#define ST2_BYTES 32768         // stage: A 16K (128 rows x 128B) | B 16K (64 k x 256B)
#define OFF_B2   16384
#define GEMM1_SMEM (3*ST2_BYTES)
#define STG_STRIDE 129
#define GEMM_QKV_SMEM (3*ST2_BYTES)

__device__ __forceinline__ void ldm_a2(uint32_t base, int rowbase, int s,
                                       uint32_t* f, int lane) {
    int row = rowbase + (lane & 7) + 8*((lane>>3)&1);
    int ch  = 2*s + (lane>>4);
    uint32_t a = base + row*128 + (((uint32_t)(ch ^ (row & 7))) << 4);
    LDSM4(f, a);
}
__device__ __forceinline__ void ldm_b2(uint32_t base, int s, int cb,
                                       uint32_t* f, int lane) {
    int k  = 16*s + (lane & 7) + 8*((lane>>3)&1);
    int ch = cb + (lane>>4);
    uint32_t a = base + k*256 + (((uint32_t)(ch ^ (k&7))) << 4);
    LDSM4T(f, a);
}

__device__ __forceinline__ void issue_stage2(
        const __half* __restrict__ Ah, const __half* __restrict__ Bh,
        int K, int N, int m0, int n0, int k0, uint32_t st, int tid) {
    #pragma unroll
    for (int i = 0; i < 4; i++) {
        int g = tid + i*GT;
        int m = g >> 3, c = g & 7;
        size_t ga = (size_t)(m0 + m)*K + k0 + c*8;
        uint32_t sa = st + m*128 + (((uint32_t)(c ^ (m & 7))) << 4);
        CP_ASYNC16(sa, Ah + ga);
    }
    #pragma unroll
    for (int i = 0; i < 4; i++) {
        int g = tid + i*GT;
        int k = g >> 4, cn = g & 15;
        size_t gb = (size_t)(k0 + k)*N + n0 + cn*8;
        uint32_t sb = st + OFF_B2 + k*256 + (((uint32_t)(cn ^ (k&7))) << 4);
        CP_ASYNC16(sb, Bh + gb);
    }
}

__device__ __forceinline__ void gemm1_mainloop(
        const __half* __restrict__ Ah, const __half* __restrict__ Bh,
        int K, int N, int m0, int n0, uint32_t sb, int tid,
        int lane, int wm, int wn, float acc[4][4][4]) {
    const int NK = K / 64;
    #pragma unroll
    for (int p = 0; p < 2; p++) {
        issue_stage2(Ah, Bh, K, N, m0, n0, p*64, sb + p*ST2_BYTES, tid);
        CP_COMMIT();
    }
    for (int kt = 0; kt < NK; kt++) {
        CP_WAIT(1);
        __syncthreads();
        uint32_t st = sb + (kt % 3)*ST2_BYTES;
        if (kt + 2 < NK)
            issue_stage2(Ah, Bh, K, N, m0, n0, (kt+2)*64,
                         sb + ((kt+2) % 3)*ST2_BYTES, tid);
        CP_COMMIT();
        #pragma unroll
        for (int s = 0; s < 4; s++) {
            uint32_t af[4][4];
            #pragma unroll
            for (int mi = 0; mi < 4; mi++)
                ldm_a2(st, wm*64 + mi*16, s, af[mi], lane);
            #pragma unroll
            for (int nj = 0; nj < 2; nj++) {
                uint32_t bf[4];
                ldm_b2(st + OFF_B2, s, wn*4 + nj*2, bf, lane);
                #pragma unroll
                for (int mi = 0; mi < 4; mi++) {
                    MMA16(acc[mi][nj*2],   af[mi], bf[0], bf[1]);
                    MMA16(acc[mi][nj*2+1], af[mi], bf[2], bf[3]);
                }
            }
        }
    }
    CP_WAIT(0);
    __syncthreads();
}

// ==================== QKV GEMM: 1-term, fused RoPE epilogue ===================
__global__ __launch_bounds__(GT, 2)
void hmma_gemm_qkv(const __half* __restrict__ Ah, const __half* __restrict__ Bh,
                   const float* __restrict__ cum) {
    extern __shared__ char smraw[];
    uint32_t sb = smem_u32(smraw);
    int tid = threadIdx.x;
    int lane = tid & 31, warp = tid >> 5;
    int wm = warp >> 2, wn = warp & 3;
    int m0 = blockIdx.y * 128, n0 = blockIdx.x * 128;

    float acc[4][4][4];
    #pragma unroll
    for (int a = 0; a < 4; a++)
        #pragma unroll
        for (int b = 0; b < 4; b++)
            #pragma unroll
            for (int c = 0; c < 4; c++) acc[a][b][c] = 0.0f;

    gemm1_mainloop(Ah, Bh, Cn, N_QKV, m0, n0, sb, tid, lane, wm, wn, acc);

    float* stg = (float*)smraw;
    int rq = lane >> 2, cq = (lane & 3) << 1;
    #pragma unroll
    for (int mi = 0; mi < 4; mi++) {
        int r = wm*64 + mi*16 + rq;
        #pragma unroll
        for (int ni = 0; ni < 4; ni++) {
            int cc = wn*32 + ni*8 + cq;
            stg[r*STG_STRIDE + cc]       = acc[mi][ni][0];
            stg[r*STG_STRIDE + cc + 1]   = acc[mi][ni][1];
            stg[(r+8)*STG_STRIDE + cc]   = acc[mi][ni][2];
            stg[(r+8)*STG_STRIDE + cc+1] = acc[mi][ni][3];
        }
    }
    __syncthreads();

    int r   = tid & 127;
    int seg = tid >> 7;
    int row = m0 + r;
    int bb = row >> 10, tt = row & 1023;
    int sec  = n0 >> 11;                   // 0=q, 1=k, 2=v
    int habs = (n0 & 2047) >> 7;
    float csc = cum[bb*Tn + tt];
    size_t obase = (((size_t)(bb*Hn + habs))*Tn + tt) * HDn;
    const float* srow = stg + r*STG_STRIDE;
    const float* csr = g_cs + row*64;
    const float* snr = g_sn + row*64;

    if (sec == 2) {
        float ev = expf(csc);
        int c0 = seg*64;
        #pragma unroll
        for (int c = c0; c < c0 + 64; c += 2)
            ((uint32_t*)g_vh)[(obase + c) >> 1] = pack16(srow[c]*ev, srow[c+1]*ev);
    } else {
        float ovr = (sec == 0) ? 1.0f : csc;
        __half* dst = (sec == 0) ? g_qh : g_kh;
        int j0 = seg*32;
        #pragma unroll
        for (int j = j0; j < j0 + 32; j += 2) {
            float s1a = srow[j],   s2a = srow[j+64];
            float s1b = srow[j+1], s2b = srow[j+65];
            float ca = csr[j], sa = snr[j], cb = csr[j+1], sbn = snr[j+1];
            float lo_a = s1a*ca - s2a*sa, hi_a = s2a*ca + s1a*sa;
            float lo_b = s1b*cb - s2b*sbn, hi_b = s2b*cb + s1b*sbn;
            if (j == 62) hi_b = ovr;
            ((uint32_t*)dst)[(obase + j) >> 1]      = pack16(lo_a, lo_b);
            ((uint32_t*)dst)[(obase + 64 + j) >> 1] = pack16(hi_a, hi_b);
        }
    }
}

// ==================== proj GEMM: 1-term fp16 ==================================
__global__ __launch_bounds__(GT, 2)
void hmma_gemm_o(const __half* __restrict__ Ah, const __half* __restrict__ Bh,
                 float* __restrict__ Cg, int M, int N, int K) {
    extern __shared__ char smraw[];
    uint32_t sb = smem_u32(smraw);
    int tid = threadIdx.x;
    int lane = tid & 31, warp = tid >> 5;
    int wm = warp >> 2, wn = warp & 3;
    int m0 = blockIdx.y * 128, n0 = blockIdx.x * 128;

    float acc[4][4][4];
    #pragma unroll
    for (int a = 0; a < 4; a++)
        #pragma unroll
        for (int b = 0; b < 4; b++)
            #pragma unroll
            for (int c = 0; c < 4; c++) acc[a][b][c] = 0.0f;

    gemm1_mainloop(Ah, Bh, K, N, m0, n0, sb, tid, lane, wm, wn, acc);

    int rq = lane >> 2, cq = (lane & 3) << 1;
    #pragma unroll
    for (int mi = 0; mi < 4; mi++) {
        int r = m0 + wm*64 + mi*16 + rq;
        #pragma unroll
        for (int ni = 0; ni < 4; ni++) {
            int cc = n0 + wn*32 + ni*8 + cq;
            *(float2*)&Cg[(size_t)r*N + cc] =
                make_float2(acc[mi][ni][0], acc[mi][ni][1]);
            *(float2*)&Cg[(size_t)(r+8)*N + cc] =
                make_float2(acc[mi][ni][2], acc[mi][ni][3]);
        }
    }
}

// ---------------- flash attention: 64 q-rows/CTA (R13) -----------------------
// smem: Q 16K | 2 x (K 16K, V 16K) | 2 x pads 256B
#define A_Q    0
#define A_BUF  16384
#define A_PADS (16384 + 65536)
#define ATTN_SMEM (A_PADS + 512)
#define SCALE_A 0.08838834764831843f
#define NEG_A  -1.0e30f

__device__ __forceinline__ void attn_load_tile(uint32_t sb, int buf, int bh,
                                               int b, int kb,
                                               const int* __restrict__ pad,
                                               int tid) {
    uint32_t base = sb + A_BUF + buf*32768;
    #pragma unroll
    for (int i = 0; i < 8; i++) {
        int g = tid + i*128;
        int row = g >> 4, ch = g & 15;
        size_t off = ((size_t)bh*Tn + kb + row)*HDn + ch*8;
        uint32_t sw = row*256 + (((uint32_t)(ch ^ (row & 7))) << 4);
        CP_ASYNC16(base + sw,         g_kh + off);
        CP_ASYNC16(base + 16384 + sw, g_vh + off);
    }
    if (tid < 16)
        CP_ASYNC16(sb + A_PADS + buf*256 + tid*16, pad + b*Tn + kb + tid*4);
}

__global__ __launch_bounds__(128, 2)
void attn_hmma(const int* __restrict__ pad) {
    extern __shared__ char smraw[];
    uint32_t sb = smem_u32(smraw);
    int tid = threadIdx.x, lane = tid & 31, w = tid >> 5;
    int mtile = blockIdx.x;
    int bh = blockIdx.y;
    int b = bh >> 4, h = bh & 15;
    int q0 = mtile*64;

    #pragma unroll
    for (int i = 0; i < 8; i++) {
        int g = tid + i*128;
        int row = g >> 4, ch = g & 15;
        size_t off = ((size_t)bh*Tn + q0 + row)*HDn + ch*8;
        uint32_t sw = row*256 + (((uint32_t)(ch ^ (row & 7))) << 4);
        CP_ASYNC16(sb + A_Q + sw, g_qh + off);
    }
    attn_load_tile(sb, 0, bh, b, 0, pad, tid);
    CP_COMMIT();

    float o[16][4];
    #pragma unroll
    for (int nt = 0; nt < 16; nt++)
        #pragma unroll
        for (int e = 0; e < 4; e++) o[nt][e] = 0.0f;
    float m0f = -3.0e38f, m1f = -3.0e38f, l0f = 0.0f, l1f = 0.0f;

    int rq = lane >> 2, cq2 = (lane & 3) << 1;
    int qg0 = q0 + w*16 + rq, qg1 = qg0 + 8;

    for (int n = 0; n <= mtile; n++) {
        int cur = n & 1;
        if (n < mtile) {
            attn_load_tile(sb, cur ^ 1, bh, b, (n+1)*64, pad, tid);
            CP_COMMIT();
            CP_WAIT(1);
        } else {
            CP_WAIT(0);
        }
        __syncthreads();

        uint32_t bufb = sb + A_BUF + cur*32768;
        int kb = n*64;

        float sa[8][4];
        #pragma unroll
        for (int nt = 0; nt < 8; nt++)
            #pragma unroll
            for (int e = 0; e < 4; e++) sa[nt][e] = 0.0f;

        #pragma unroll
        for (int s = 0; s < 8; s++) {
            uint32_t qhf[4];
            {
                int row = w*16 + (lane & 7) + 8*((lane>>3)&1);
                int ch  = 2*s + (lane>>4);
                uint32_t ad = sb + A_Q + row*256 +
                              (((uint32_t)(ch ^ (row & 7))) << 4);
                LDSM4(qhf, ad);
            }
            #pragma unroll
            for (int g4 = 0; g4 < 4; g4++) {
                uint32_t khf[4];
                int key = g4*16 + (lane & 7) + 8*((lane>>3)&1);
                int ch  = 2*s + (lane>>4);
                uint32_t ad = bufb + key*256 +
                              (((uint32_t)(ch ^ (key & 7))) << 4);
                LDSM4(khf, ad);
                MMA16(sa[2*g4],   qhf, khf[0], khf[2]);
                MMA16(sa[2*g4+1], qhf, khf[1], khf[3]);
            }
        }

        const int* padp = (const int*)(smraw + A_PADS + cur*256);
        #pragma unroll
        for (int nt = 0; nt < 8; nt++) {
            int kc = nt*8 + cq2;
            int kg = kb + kc;
            int p0 = padp[kc], p1 = padp[kc+1];
            float v;
            v = sa[nt][0]*SCALE_A; if (kg   > qg0 || !p0) v = NEG_A; sa[nt][0] = v;
            v = sa[nt][1]*SCALE_A; if (kg+1 > qg0 || !p1) v = NEG_A; sa[nt][1] = v;
            v = sa[nt][2]*SCALE_A; if (kg   > qg1 || !p0) v = NEG_A; sa[nt][2] = v;
            v = sa[nt][3]*SCALE_A; if (kg+1 > qg1 || !p1) v = NEG_A; sa[nt][3] = v;
        }

        float mx0 = -3.0e38f, mx1 = -3.0e38f;
        #pragma unroll
        for (int nt = 0; nt < 8; nt++) {
            mx0 = fmaxf(mx0, fmaxf(sa[nt][0], sa[nt][1]));
            mx1 = fmaxf(mx1, fmaxf(sa[nt][2], sa[nt][3]));
        }
        mx0 = fmaxf(mx0, __shfl_xor_sync(0xffffffffu, mx0, 1));
        mx0 = fmaxf(mx0, __shfl_xor_sync(0xffffffffu, mx0, 2));
        mx1 = fmaxf(mx1, __shfl_xor_sync(0xffffffffu, mx1, 1));
        mx1 = fmaxf(mx1, __shfl_xor_sync(0xffffffffu, mx1, 2));
        float mn0 = fmaxf(m0f, mx0), mn1 = fmaxf(m1f, mx1);
        float al0 = __expf(m0f - mn0), al1 = __expf(m1f - mn1);
        m0f = mn0; m1f = mn1;
        float s0 = 0.0f, s1 = 0.0f;
        #pragma unroll
        for (int nt = 0; nt < 8; nt++) {
            sa[nt][0] = __expf(sa[nt][0] - mn0); s0 += sa[nt][0];
            sa[nt][1] = __expf(sa[nt][1] - mn0); s0 += sa[nt][1];
            sa[nt][2] = __expf(sa[nt][2] - mn1); s1 += sa[nt][2];
            sa[nt][3] = __expf(sa[nt][3] - mn1); s1 += sa[nt][3];
        }
        s0 += __shfl_xor_sync(0xffffffffu, s0, 1);
        s0 += __shfl_xor_sync(0xffffffffu, s0, 2);
        s1 += __shfl_xor_sync(0xffffffffu, s1, 1);
        s1 += __shfl_xor_sync(0xffffffffu, s1, 2);
        l0f = l0f*al0 + s0;
        l1f = l1f*al1 + s1;
        #pragma unroll
        for (int nt = 0; nt < 16; nt++) {
            o[nt][0] *= al0; o[nt][1] *= al0;
            o[nt][2] *= al1; o[nt][3] *= al1;
        }

        #pragma unroll
        for (int j = 0; j < 4; j++) {
            uint32_t aph[4];
            aph[0] = pack16(sa[2*j][0],   sa[2*j][1]);
            aph[1] = pack16(sa[2*j][2],   sa[2*j][3]);
            aph[2] = pack16(sa[2*j+1][0], sa[2*j+1][1]);
            aph[3] = pack16(sa[2*j+1][2], sa[2*j+1][3]);
            #pragma unroll
            for (int u = 0; u < 8; u++) {
                uint32_t vhf[4];
                int key = j*16 + (lane & 7) + 8*((lane>>3)&1);
                int ch  = u*2 + (lane>>4);
                uint32_t ad = bufb + 16384 + key*256 +
                              (((uint32_t)(ch ^ (key & 7))) << 4);
                LDSM4T(vhf, ad);
                MMA16(o[2*u],   aph, vhf[0], vhf[1]);
                MMA16(o[2*u+1], aph, vhf[2], vhf[3]);
            }
        }
        __syncthreads();
    }

    float i0 = 1.0f / l0f, i1 = 1.0f / l1f;
    size_t r0g = (size_t)(b*Tn + q0 + w*16 + rq)*Cn + h*HDn;
    size_t r1g = r0g + (size_t)8*Cn;
    #pragma unroll
    for (int nt = 0; nt < 16; nt++) {
        int col = nt*8 + cq2;
        ((uint32_t*)g_yh)[(r0g + col) >> 1] = pack16(o[nt][0]*i0, o[nt][1]*i0);
        ((uint32_t*)g_yh)[(r1g + col) >> 1] = pack16(o[nt][2]*i1, o[nt][3]*i1);
    }
}

// ---------------- launcher ----------------------------------------------------
extern "C" void kernel_launch(void* const* d_in, const int* in_sizes, int n_in,
                              void* d_out, int out_size) {
    const float* x    = (const float*)d_in[0];
    const float* cum  = (const float*)d_in[1];
    const int*   tok  = (const int*)d_in[2];
    const int*   padm = (const int*)d_in[3];
    const float* Wa   = (const float*)d_in[4];
    const float* Wp   = (const float*)d_in[5];
    float* out = (float*)d_out;

    __half *xh, *wa, *wp, *yh;
    cudaGetSymbolAddress((void**)&xh, g_xh);
    cudaGetSymbolAddress((void**)&wa, g_Wa);
    cudaGetSymbolAddress((void**)&wp, g_Wp);
    cudaGetSymbolAddress((void**)&yh, g_yh);

    cudaFuncSetAttribute(attn_hmma,
                         cudaFuncAttributeMaxDynamicSharedMemorySize, ATTN_SMEM);
    cudaFuncSetAttribute(hmma_gemm_qkv,
                         cudaFuncAttributeMaxDynamicSharedMemorySize, GEMM_QKV_SMEM);
    cudaFuncSetAttribute(hmma_gemm_o,
                         cudaFuncAttributeMaxDynamicSharedMemorySize, GEMM1_SMEM);

    prep_fused<<<CVT_BLOCKS + 1, 1024>>>(tok, x, Wa, Wp);
    rope_kernel<<<(M_ALL*64)/256, 256>>>();

    hmma_gemm_qkv<<<dim3(N_QKV/128, M_ALL/128), GT, GEMM_QKV_SMEM>>>(xh, wa, cum);

    attn_hmma<<<dim3(Tn/64, Bn*Hn), 128, ATTN_SMEM>>>(padm);

    hmma_gemm_o<<<dim3(Cn/128, M_ALL/128), GT, GEMM1_SMEM>>>(
        yh, wp, out, M_ALL, Cn, Cn);
}